// round 2
// baseline (speedup 1.0000x reference)
#include <cuda_runtime.h>
#include <math.h>

#define BATCH 256
#define PRIOR 60
#define FRAMES 240
#define PRED 180
#define POSE 768
#define CHUNK 10
#define EPSF 1e-5f

// ---------------- scratch (device globals; no allocations allowed) ----------------
__device__ __align__(16) float g_P1[BATCH * PRED * POSE];   // conv1 output
__device__ __align__(16) float g_P2[BATCH * PRED * POSE];   // conv2 output (chunk-updated in place)
__device__ __align__(16) float g_t1[BATCH * POSE];
__device__ __align__(16) float g_mem[BATCH * POSE];
__device__ __align__(16) float g_t2[BATCH * POSE];
__device__ __align__(16) float g_mem2[BATCH * POSE];
__device__ __align__(16) float g_penc1[BATCH * CHUNK];
__device__ __align__(16) float g_penc2[BATCH * CHUNK];
__device__ __align__(16) float g_G[POSE * CHUNK];
__device__ __align__(16) float g_W1T[POSE * POSE];          // post_w1 transposed
__device__ __align__(16) float g_WcT[POSE * POSE];          // post_w2 @ post_w1   [d][h]
__device__ __align__(16) float g_bc[POSE];                  // post_w2 @ post_b1 + post_b2

// compile-time scratch-buffer selector (avoids any host-side symbol queries)
template <int ID>
__device__ __forceinline__ float* SB() {
    if constexpr (ID == 1) return g_P1;
    else if constexpr (ID == 2) return g_P2;
    else if constexpr (ID == 3) return g_t1;
    else if constexpr (ID == 4) return g_mem;
    else if constexpr (ID == 5) return g_t2;
    else if constexpr (ID == 6) return g_mem2;
    else if constexpr (ID == 7) return g_W1T;
    else return g_WcT;  // 8
}

// ---------------- helpers ----------------
__device__ __forceinline__ float blockReduceSum(float v) {
    __shared__ float red[32];
    int lane = threadIdx.x & 31, wid = threadIdx.x >> 5;
#pragma unroll
    for (int o = 16; o > 0; o >>= 1) v += __shfl_down_sync(0xffffffffu, v, o);
    if (lane == 0) red[wid] = v;
    __syncthreads();
    int nw = (blockDim.x + 31) >> 5;
    v = (threadIdx.x < nw) ? red[threadIdx.x] : 0.f;
    if (wid == 0) {
#pragma unroll
        for (int o = 16; o > 0; o >>= 1) v += __shfl_down_sync(0xffffffffu, v, o);
        if (lane == 0) red[0] = v;
    }
    __syncthreads();
    return red[0];
}

// ---------------- conv(k=3,p=1) + bias + relu + BN(eval), implicit GEMM ----------------
// input: [B, IC, 768] (SRC=-1 -> arg pointer, else scratch), w: [OC, IC, 3], out: scratch DST
template <int IC, int OC, int SRC, int DST>
__global__ __launch_bounds__(256) void conv_bn_kernel(
    const float* __restrict__ xarg, const float* __restrict__ w,
    const float* __restrict__ cbias,
    const float* __restrict__ bng, const float* __restrict__ bnb,
    const float* __restrict__ bnm, const float* __restrict__ bnv)
{
    constexpr int K3 = IC * 3;
    constexpr int BK = 18;             // multiple of 3; divides 180 and 540
    const float* xin = (SRC < 0) ? xarg : SB<SRC>();
    float* out = SB<DST>();
    __shared__ float As[BK][68];
    __shared__ float Bs[BK][68];
    int b = blockIdx.z;
    int l0 = blockIdx.x * 64;
    int oc0 = blockIdx.y * 64;
    int tid = threadIdx.x;
    int tx = tid & 15, ty = tid >> 4;
    const float* xb = xin + (size_t)b * IC * POSE;

    float acc[4][4];
#pragma unroll
    for (int i = 0; i < 4; i++)
#pragma unroll
        for (int j = 0; j < 4; j++) acc[i][j] = 0.f;

    for (int k0 = 0; k0 < K3; k0 += BK) {
        for (int i = tid; i < 64 * BK; i += 256) {
            int oc = i / BK, kk = i - (i / BK) * BK;
            int goc = oc0 + oc;
            As[kk][oc] = (goc < OC) ? w[goc * K3 + k0 + kk] : 0.f;
        }
        for (int i = tid; i < 64 * BK; i += 256) {
            int kk = i >> 6, l = i & 63;
            int gk = k0 + kk;
            int ic = gk / 3, koff = gk - ic * 3;
            int gl = l0 + l + koff - 1;
            Bs[kk][l] = (gl >= 0 && gl < POSE) ? xb[ic * POSE + gl] : 0.f;
        }
        __syncthreads();
#pragma unroll
        for (int kk = 0; kk < BK; kk++) {
            float4 av = *(const float4*)&As[kk][ty * 4];
            float4 bv = *(const float4*)&Bs[kk][tx * 4];
            float a[4] = {av.x, av.y, av.z, av.w};
            float bb[4] = {bv.x, bv.y, bv.z, bv.w};
#pragma unroll
            for (int i = 0; i < 4; i++)
#pragma unroll
                for (int j = 0; j < 4; j++) acc[i][j] = fmaf(a[i], bb[j], acc[i][j]);
        }
        __syncthreads();
    }

#pragma unroll
    for (int i = 0; i < 4; i++) {
        int oc = oc0 + ty * 4 + i;
        if (oc >= OC) continue;
        float bi = cbias[oc];
        float scale = rsqrtf(bnv[oc] + EPSF) * bng[oc];
        float mm = bnm[oc], bt = bnb[oc];
        float4 o;
        float r[4];
#pragma unroll
        for (int j = 0; j < 4; j++) {
            float y = acc[i][j] + bi;
            y = fmaxf(y, 0.f);
            r[j] = (y - mm) * scale + bt;
        }
        o.x = r[0]; o.y = r[1]; o.z = r[2]; o.w = r[3];
        *(float4*)(out + ((size_t)b * OC + oc) * POSE + l0 + tx * 4) = o;
    }
}

// ---------------- generic linear: C[m,n] = sum_k A[m,k]*W[n,k] + bias[n] ----------------
// BM=128, BN=64, BK=16, 256 threads, TM=8, TN=4. Requires M%128==0, N%64==0, K%16==0.
// AID/WID: -1 -> use arg pointer, else scratch id. CID: scratch id for output.
template <int AID, int WID, int CID, bool HASBIAS>
__global__ __launch_bounds__(256) void lin_kernel(
    const float* __restrict__ Aarg, size_t strideA,
    const float* __restrict__ Warg, const float* __restrict__ bias,
    int N, int K)
{
    const float* A = (AID < 0) ? Aarg : SB<AID>();
    const float* W = (WID < 0) ? Warg : SB<WID>();
    float* C = SB<CID>();
    __shared__ float As[16][132];
    __shared__ float Bs[16][68];
    int n0 = blockIdx.x * 64;
    int m0 = blockIdx.y * 128;
    int tid = threadIdx.x;
    int tx = tid & 15, ty = tid >> 4;

    const float* arow = A + (size_t)(m0 + (tid >> 1)) * strideA + ((tid & 1) * 8);
    const float* wrow = W + (size_t)(n0 + (tid >> 2)) * K + ((tid & 3) * 4);
    int am = tid >> 1, ak = (tid & 1) * 8;
    int bn = tid >> 2, bk = (tid & 3) * 4;

    float acc[8][4];
#pragma unroll
    for (int i = 0; i < 8; i++)
#pragma unroll
        for (int j = 0; j < 4; j++) acc[i][j] = 0.f;

    for (int k0 = 0; k0 < K; k0 += 16) {
        float4 a0 = *(const float4*)(arow + k0);
        float4 a1 = *(const float4*)(arow + k0 + 4);
        float4 b0 = *(const float4*)(wrow + k0);
        As[ak + 0][am] = a0.x; As[ak + 1][am] = a0.y; As[ak + 2][am] = a0.z; As[ak + 3][am] = a0.w;
        As[ak + 4][am] = a1.x; As[ak + 5][am] = a1.y; As[ak + 6][am] = a1.z; As[ak + 7][am] = a1.w;
        Bs[bk + 0][bn] = b0.x; Bs[bk + 1][bn] = b0.y; Bs[bk + 2][bn] = b0.z; Bs[bk + 3][bn] = b0.w;
        __syncthreads();
#pragma unroll
        for (int kk = 0; kk < 16; kk++) {
            float4 av0 = *(const float4*)&As[kk][ty * 8];
            float4 av1 = *(const float4*)&As[kk][ty * 8 + 4];
            float4 bv = *(const float4*)&Bs[kk][tx * 4];
            float a[8] = {av0.x, av0.y, av0.z, av0.w, av1.x, av1.y, av1.z, av1.w};
            float bb[4] = {bv.x, bv.y, bv.z, bv.w};
#pragma unroll
            for (int i = 0; i < 8; i++)
#pragma unroll
                for (int j = 0; j < 4; j++) acc[i][j] = fmaf(a[i], bb[j], acc[i][j]);
        }
        __syncthreads();
    }

    float bj[4];
#pragma unroll
    for (int j = 0; j < 4; j++) bj[j] = HASBIAS ? bias[n0 + tx * 4 + j] : 0.f;
#pragma unroll
    for (int i = 0; i < 8; i++) {
        int m = m0 + ty * 8 + i;
        float4 o;
        o.x = acc[i][0] + bj[0]; o.y = acc[i][1] + bj[1];
        o.z = acc[i][2] + bj[2]; o.w = acc[i][3] + bj[3];
        *(float4*)(C + (size_t)m * N + n0 + tx * 4) = o;
    }
}

// ---------------- final GEMM with gathered rows: out = concat(x, P2) @ Wc^T + bc --------
// M = 61440 (= B*240), N = K = 768
__global__ __launch_bounds__(256) void final_kernel(
    const float* __restrict__ x, float* __restrict__ C)
{
    const float* P2 = g_P2;
    const float* WcT = g_WcT;
    const float* bc = g_bc;
    __shared__ float As[16][132];
    __shared__ float Bs[16][68];
    int n0 = blockIdx.x * 64;
    int m0 = blockIdx.y * 128;
    int tid = threadIdx.x;
    int tx = tid & 15, ty = tid >> 4;

    int row = m0 + (tid >> 1);
    int b = row / FRAMES, f = row - b * FRAMES;
    const float* arow = (f < PRIOR)
        ? x + ((size_t)b * PRIOR + f) * POSE + ((tid & 1) * 8)
        : P2 + ((size_t)b * PRED + (f - PRIOR)) * POSE + ((tid & 1) * 8);
    const float* wrow = WcT + (size_t)(n0 + (tid >> 2)) * POSE + ((tid & 3) * 4);
    int am = tid >> 1, ak = (tid & 1) * 8;
    int bn = tid >> 2, bk = (tid & 3) * 4;

    float acc[8][4];
#pragma unroll
    for (int i = 0; i < 8; i++)
#pragma unroll
        for (int j = 0; j < 4; j++) acc[i][j] = 0.f;

    for (int k0 = 0; k0 < POSE; k0 += 16) {
        float4 a0 = *(const float4*)(arow + k0);
        float4 a1 = *(const float4*)(arow + k0 + 4);
        float4 b0 = *(const float4*)(wrow + k0);
        As[ak + 0][am] = a0.x; As[ak + 1][am] = a0.y; As[ak + 2][am] = a0.z; As[ak + 3][am] = a0.w;
        As[ak + 4][am] = a1.x; As[ak + 5][am] = a1.y; As[ak + 6][am] = a1.z; As[ak + 7][am] = a1.w;
        Bs[bk + 0][bn] = b0.x; Bs[bk + 1][bn] = b0.y; Bs[bk + 2][bn] = b0.z; Bs[bk + 3][bn] = b0.w;
        __syncthreads();
#pragma unroll
        for (int kk = 0; kk < 16; kk++) {
            float4 av0 = *(const float4*)&As[kk][ty * 8];
            float4 av1 = *(const float4*)&As[kk][ty * 8 + 4];
            float4 bv = *(const float4*)&Bs[kk][tx * 4];
            float a[8] = {av0.x, av0.y, av0.z, av0.w, av1.x, av1.y, av1.z, av1.w};
            float bb[4] = {bv.x, bv.y, bv.z, bv.w};
#pragma unroll
            for (int i = 0; i < 8; i++)
#pragma unroll
                for (int j = 0; j < 4; j++) acc[i][j] = fmaf(a[i], bb[j], acc[i][j]);
        }
        __syncthreads();
    }

    float bj[4];
#pragma unroll
    for (int j = 0; j < 4; j++) bj[j] = bc[n0 + tx * 4 + j];
#pragma unroll
    for (int i = 0; i < 8; i++) {
        int m = m0 + ty * 8 + i;
        float4 o;
        o.x = acc[i][0] + bj[0]; o.y = acc[i][1] + bj[1];
        o.z = acc[i][2] + bj[2]; o.w = acc[i][3] + bj[3];
        *(float4*)(C + (size_t)m * POSE + n0 + tx * 4) = o;
    }
}

// ---------------- SP memory net: score -> sigmoid blend (in place on P2[:, :10, :]) -----
__global__ __launch_bounds__(256) void sp_blend_kernel()
{
    int c = blockIdx.x, b = blockIdx.y;
    float* pc = g_P2 + ((size_t)b * PRED + c) * POSE;
    const float* mb = g_mem + (size_t)b * POSE;
    float s = 0.f;
    for (int d = threadIdx.x; d < POSE; d += 256) s += mb[d] * pc[d];
    float total = blockReduceSum(s);
    float sg = 1.f / (1.f + expf(-total));
    for (int d = threadIdx.x; d < POSE; d += 256)
        pc[d] = sg * pc[d] + (1.f - sg) * mb[d];
}

// ---------------- penc layer 1: [B,10] = P2[:, :10, :].flat @ tmm_w1^T + b ----------------
__global__ __launch_bounds__(256) void penc1_kernel(const float* __restrict__ w,
                                                    const float* __restrict__ bias)
{
    int n = blockIdx.x, b = blockIdx.y;
    const float* a = g_P2 + (size_t)b * PRED * POSE;  // frames 0..9 contiguous: 7680
    const float* wr = w + (size_t)n * (CHUNK * POSE);
    float s = 0.f;
    for (int k = threadIdx.x; k < CHUNK * POSE; k += 256) s += a[k] * wr[k];
    float total = blockReduceSum(s);
    if (threadIdx.x == 0) g_penc1[b * CHUNK + n] = total + bias[n];
}

__global__ void penc2_kernel(const float* __restrict__ w, const float* __restrict__ bias)
{
    int b = threadIdx.x;  // 256 threads
    float in[CHUNK];
#pragma unroll
    for (int j = 0; j < CHUNK; j++) in[j] = g_penc1[b * CHUNK + j];
#pragma unroll
    for (int n = 0; n < CHUNK; n++) {
        float s = bias[n];
#pragma unroll
        for (int j = 0; j < CHUNK; j++) s = fmaf(in[j], w[n * CHUNK + j], s);
        g_penc2[b * CHUNK + n] = s;
    }
}

// ---------------- G = mem2^T @ penc2 : [768,10] (reduce over batch) ----------------
__global__ __launch_bounds__(256) void gmat_kernel()
{
    int t = blockIdx.x * 256 + threadIdx.x;  // 7680 threads
    int c = t / POSE, h = t - c * POSE;
    float s = 0.f;
    for (int b = 0; b < BATCH; b++)
        s = fmaf(g_mem2[(size_t)b * POSE + h], g_penc2[b * CHUNK + c], s);
    g_G[h * CHUNK + c] = s;
}

// ---------------- score2 = mem2 @ G, softmax over CHUNK, scale P2 chunk in place --------
__global__ __launch_bounds__(320) void tm_scale_kernel()
{
    __shared__ float Gs[POSE * CHUNK];
    __shared__ float sc[CHUNK];
    __shared__ float soft[CHUNK];
    int b = blockIdx.x;
    for (int i = threadIdx.x; i < POSE * CHUNK; i += 320) Gs[i] = g_G[i];
    __syncthreads();
    int wid = threadIdx.x >> 5, lane = threadIdx.x & 31;
    float s = 0.f;
    const float* mb = g_mem2 + (size_t)b * POSE;
    for (int h = lane; h < POSE; h += 32) s = fmaf(mb[h], Gs[h * CHUNK + wid], s);
#pragma unroll
    for (int o = 16; o > 0; o >>= 1) s += __shfl_down_sync(0xffffffffu, s, o);
    if (lane == 0) sc[wid] = s;
    __syncthreads();
    if (threadIdx.x == 0) {
        float mx = -1e30f;
#pragma unroll
        for (int c = 0; c < CHUNK; c++) mx = fmaxf(mx, sc[c]);
        float ssum = 0.f;
#pragma unroll
        for (int c = 0; c < CHUNK; c++) { float e = expf(sc[c] - mx); soft[c] = e; ssum += e; }
        float inv = 1.f / ssum;
#pragma unroll
        for (int c = 0; c < CHUNK; c++) soft[c] *= inv;
    }
    __syncthreads();
    float* pb = g_P2 + (size_t)b * PRED * POSE;
    for (int i = threadIdx.x; i < CHUNK * POSE; i += 320) {
        int c = i / POSE;
        pb[i] *= (1.f + soft[c]);
    }
}

// ---------------- 768x768 transpose: g_W1T = post_w1^T ----------------
__global__ void transpose_kernel(const float* __restrict__ in)
{
    __shared__ float tile[32][33];
    int x0 = blockIdx.x * 32, y0 = blockIdx.y * 32;
    for (int dy = threadIdx.y; dy < 32; dy += 8)
        tile[dy][threadIdx.x] = in[(size_t)(y0 + dy) * POSE + x0 + threadIdx.x];
    __syncthreads();
    for (int dy = threadIdx.y; dy < 32; dy += 8)
        g_W1T[(size_t)(x0 + dy) * POSE + y0 + threadIdx.x] = tile[threadIdx.x][dy];
}

// ---------------- bc = post_w2 @ post_b1 + post_b2 ----------------
__global__ void bc_kernel(const float* __restrict__ W2, const float* __restrict__ b1,
                          const float* __restrict__ b2)
{
    int d = blockIdx.x * 256 + threadIdx.x;
    if (d >= POSE) return;
    float s = 0.f;
    for (int j = 0; j < POSE; j++) s = fmaf(W2[(size_t)d * POSE + j], b1[j], s);
    g_bc[d] = s + b2[d];
}

// ---------------- launch ----------------
extern "C" void kernel_launch(void* const* d_in, const int* in_sizes, int n_in,
                              void* d_out, int out_size)
{
    const float* x       = (const float*)d_in[0];
    const float* conv1_w = (const float*)d_in[1];
    const float* conv1_b = (const float*)d_in[2];
    const float* bn1_g   = (const float*)d_in[3];
    const float* bn1_b   = (const float*)d_in[4];
    const float* bn1_m   = (const float*)d_in[5];
    const float* bn1_v   = (const float*)d_in[6];
    const float* conv2_w = (const float*)d_in[7];
    const float* conv2_b = (const float*)d_in[8];
    const float* bn2_g   = (const float*)d_in[9];
    const float* bn2_b   = (const float*)d_in[10];
    const float* bn2_m   = (const float*)d_in[11];
    const float* bn2_v   = (const float*)d_in[12];
    const float* sp_w1   = (const float*)d_in[13];
    const float* sp_b1   = (const float*)d_in[14];
    const float* sp_w2   = (const float*)d_in[15];
    const float* sp_b2   = (const float*)d_in[16];
    const float* tmc_w1  = (const float*)d_in[17];
    const float* tmc_b1  = (const float*)d_in[18];
    const float* tmc_w2  = (const float*)d_in[19];
    const float* tmc_b2  = (const float*)d_in[20];
    const float* tmm_w1  = (const float*)d_in[21];
    const float* tmm_b1  = (const float*)d_in[22];
    const float* tmm_w2  = (const float*)d_in[23];
    const float* tmm_b2  = (const float*)d_in[24];
    const float* post_w1 = (const float*)d_in[25];
    const float* post_b1 = (const float*)d_in[26];
    const float* post_w2 = (const float*)d_in[27];
    const float* post_b2 = (const float*)d_in[28];
    float* out = (float*)d_out;

    // pred_conv: conv1 x -> g_P1, conv2 g_P1 -> g_P2
    dim3 convGrid(POSE / 64, 3, BATCH);
    conv_bn_kernel<PRIOR, PRED, -1, 1><<<convGrid, 256>>>(
        x, conv1_w, conv1_b, bn1_g, bn1_b, bn1_m, bn1_v);
    conv_bn_kernel<PRED, PRED, 1, 2><<<convGrid, 256>>>(
        nullptr, conv2_w, conv2_b, bn2_g, bn2_b, bn2_m, bn2_v);

    // tail = x[:, 50:60, :].reshape(B, 7680): base x + 50*768, row stride 60*768
    dim3 gTail(POSE / 64, BATCH / 128);
    lin_kernel<-1, -1, 3, true><<<gTail, 256>>>(x + 50 * POSE, (size_t)PRIOR * POSE,
                                                sp_w1, sp_b1, POSE, CHUNK * POSE);
    lin_kernel<3, -1, 4, true><<<gTail, 256>>>(nullptr, POSE, sp_w2, sp_b2, POSE, POSE);
    lin_kernel<-1, -1, 5, true><<<gTail, 256>>>(x + 50 * POSE, (size_t)PRIOR * POSE,
                                                tmc_w1, tmc_b1, POSE, CHUNK * POSE);
    lin_kernel<5, -1, 6, true><<<gTail, 256>>>(nullptr, POSE, tmc_w2, tmc_b2, POSE, POSE);

    // SP blend (in place on g_P2 chunk)
    sp_blend_kernel<<<dim3(CHUNK, BATCH), 256>>>();

    // TM memory net
    penc1_kernel<<<dim3(CHUNK, BATCH), 256>>>(tmm_w1, tmm_b1);
    penc2_kernel<<<1, BATCH>>>(tmm_w2, tmm_b2);
    gmat_kernel<<<(POSE * CHUNK) / 256, 256>>>();
    tm_scale_kernel<<<BATCH, 320>>>();

    // collapsed post_header: g_WcT = post_w2 @ post_w1 (via g_W1T), g_bc = W2@b1 + b2
    transpose_kernel<<<dim3(24, 24), dim3(32, 8)>>>(post_w1);
    lin_kernel<-1, 7, 8, false><<<dim3(POSE / 64, POSE / 128), 256>>>(
        post_w2, POSE, nullptr, nullptr, POSE, POSE);
    bc_kernel<<<3, 256>>>(post_w2, post_b1, post_b2);

    // final: [61440, 768] @ Wc^T + bc -> out
    final_kernel<<<dim3(POSE / 64, (BATCH * FRAMES) / 128), 256>>>(x, out);
}

// round 7
// speedup vs baseline: 2.3233x; 2.3233x over previous
#include <cuda_runtime.h>
#include <math.h>
#include <stdint.h>

#define BATCH 256
#define PRIOR 60
#define FRAMES 240
#define PRED 180
#define POSE 768
#define CHUNK 10
#define EPSF 1e-5f

// ---------------- scratch (device globals; no allocations allowed) ----------------
__device__ __align__(16) float g_P1[BATCH * PRED * POSE];
__device__ __align__(16) float g_P2[BATCH * PRED * POSE];
__device__ __align__(16) float g_t1[BATCH * POSE];
__device__ __align__(16) float g_t2[BATCH * POSE];
__device__ __align__(16) float g_mem[BATCH * POSE];
__device__ __align__(16) float g_mem2[BATCH * POSE];
__device__ __align__(16) float g_penc1[BATCH * CHUNK];
__device__ __align__(16) float g_penc2[BATCH * CHUNK];
__device__ __align__(16) float g_G[POSE * CHUNK];
__device__ __align__(16) float g_W1T[POSE * POSE];
__device__ __align__(16) float g_WcT[POSE * POSE];
__device__ __align__(16) float g_bc[POSE];
__device__ __align__(16) float g_Wp1[192 * 192];    // conv1 weights padded, tf32-rounded
__device__ __align__(16) float g_Wp2[192 * 544];    // conv2 weights padded, tf32-rounded

// ---------------- tf32 helpers ----------------
__device__ __forceinline__ float tf32r(float x) {
    unsigned u;
    asm("cvt.rna.tf32.f32 %0, %1;" : "=r"(u) : "f"(x));
    return __uint_as_float(u);
}
__device__ __forceinline__ unsigned fau(float x) { return __float_as_uint(x); }

__device__ __forceinline__ void mma8(float c[4], const unsigned a[4], unsigned b0, unsigned b1) {
    asm volatile(
        "mma.sync.aligned.m16n8k8.row.col.f32.tf32.tf32.f32 "
        "{%0,%1,%2,%3}, {%4,%5,%6,%7}, {%8,%9}, {%0,%1,%2,%3};"
        : "+f"(c[0]), "+f"(c[1]), "+f"(c[2]), "+f"(c[3])
        : "r"(a[0]), "r"(a[1]), "r"(a[2]), "r"(a[3]), "r"(b0), "r"(b1));
}

// shared-tile row stride (floats): BK=32 + 4 pad -> conflict-free frag loads
#define SAS 36

// ---------------- generic tensor-core linear ----------------
// C[m,n] = sum_k A[m,k] * W[n,k] + bias[n], all fp32 in/out, tf32 mma inside.
// BM in {64,128}, BN=128, BK=32, 256 threads (8 warps).
// MODE 0: WcT precompute   A=a0(post_w2) lda=768, W=g_W1T, C=g_WcT, K=768
// MODE 1: final            A gathered from a0(x)/g_P2, W=g_WcT, bias=g_bc, C=cext, K=768
// MODE 2: tail layer1      A=a0(x+50*768) lda=46080; blockIdx.x>=6 selects tmc vs sp; K=7680
// MODE 3: tail layer2      A=g_t1/g_t2; selects sp_w2/tmc_w2; C=g_mem/g_mem2; K=768
template <int BM, int MODE>
__global__ __launch_bounds__(256) void tc_lin_kernel(
    const float* __restrict__ a0,
    const float* __restrict__ w0, const float* __restrict__ w1,
    const float* __restrict__ bi0, const float* __restrict__ bi1,
    float* __restrict__ cext)
{
    constexpr int NF = (BM == 128) ? 8 : 4;       // n-frags per warp
    constexpr int WROWS = (BM == 128) ? 4 : 2;    // warps along m
    constexpr int TPR = 256 / BM;                 // threads per A row
    constexpr int KSEG = 32 / TPR;                // k floats per thread (A)
    constexpr int AV = KSEG / 4;                  // float4s per thread (A)
    constexpr int K = (MODE == 2) ? CHUNK * POSE : POSE;

    __shared__ __align__(16) float As[BM * SAS];
    __shared__ __align__(16) float Bs[128 * SAS];

    int bx = blockIdx.x, by = blockIdx.y;
    int sel = 0, nblk = bx;
    if constexpr (MODE == 2 || MODE == 3) {
        sel = bx >= (POSE / 128);
        nblk = bx - sel * (POSE / 128);
    }
    int n0 = nblk * 128;
    int m0 = by * BM;
    int t = threadIdx.x;

    // resolve operands
    const float* W;
    const float* bias;
    float* C;
    if constexpr (MODE == 0)      { W = g_W1T;            bias = nullptr;           C = g_WcT; }
    else if constexpr (MODE == 1) { W = g_WcT;            bias = g_bc;              C = cext;  }
    else if constexpr (MODE == 2) { W = sel ? w1 : w0;    bias = sel ? bi1 : bi0;   C = sel ? g_t2 : g_t1; }
    else                          { W = sel ? w1 : w0;    bias = sel ? bi1 : bi0;   C = sel ? g_mem2 : g_mem; }

    // per-thread A pointer (k=0)
    int arow = t / TPR, akh = (t % TPR) * KSEG;
    const float* aptr;
    if constexpr (MODE == 1) {
        int row = m0 + arow;
        int b = row / FRAMES, f = row - b * FRAMES;
        aptr = (f < PRIOR)
            ? a0 + ((size_t)b * PRIOR + f) * POSE + akh
            : g_P2 + ((size_t)b * PRED + (f - PRIOR)) * POSE + akh;
    } else if constexpr (MODE == 3) {
        const float* A = sel ? g_t2 : g_t1;
        aptr = A + (size_t)(m0 + arow) * POSE + akh;
    } else {
        size_t lda = (MODE == 2) ? (size_t)PRIOR * POSE : (size_t)POSE;
        aptr = a0 + (size_t)(m0 + arow) * lda + akh;
    }
    int brow = t >> 1, bkh = (t & 1) * 16;
    const float* wptr = W + (size_t)(n0 + brow) * K + bkh;

    // warp coords
    int w = t >> 5, lane = t & 31;
    int wm = w % WROWS, wn = w / WROWS;
    int wmBase = wm * 32, wnBase = wn * 8 * NF;
    int g = lane >> 2, t4 = lane & 3;

    float c[2][NF][4];
#pragma unroll
    for (int mf = 0; mf < 2; mf++)
#pragma unroll
        for (int nf = 0; nf < NF; nf++)
#pragma unroll
            for (int i = 0; i < 4; i++) c[mf][nf][i] = 0.f;

    float4 ra[AV], rb[4];
#pragma unroll
    for (int v = 0; v < AV; v++) ra[v] = *(const float4*)(aptr + v * 4);
#pragma unroll
    for (int v = 0; v < 4; v++) rb[v] = *(const float4*)(wptr + v * 4);

    int k0 = 0;
    while (true) {
#pragma unroll
        for (int v = 0; v < AV; v++) {
            float4 q = ra[v];
            q.x = tf32r(q.x); q.y = tf32r(q.y); q.z = tf32r(q.z); q.w = tf32r(q.w);
            *(float4*)&As[arow * SAS + akh + v * 4] = q;
        }
#pragma unroll
        for (int v = 0; v < 4; v++) {
            float4 q = rb[v];
            q.x = tf32r(q.x); q.y = tf32r(q.y); q.z = tf32r(q.z); q.w = tf32r(q.w);
            *(float4*)&Bs[brow * SAS + bkh + v * 4] = q;
        }
        __syncthreads();

        bool last = (k0 + 32 >= K);
        if (!last) {
#pragma unroll
            for (int v = 0; v < AV; v++) ra[v] = *(const float4*)(aptr + k0 + 32 + v * 4);
#pragma unroll
            for (int v = 0; v < 4; v++) rb[v] = *(const float4*)(wptr + k0 + 32 + v * 4);
        }

#pragma unroll
        for (int kt = 0; kt < 4; kt++) {
            unsigned a[2][4];
#pragma unroll
            for (int mf = 0; mf < 2; mf++) {
                const float* ap = &As[(wmBase + mf * 16 + g) * SAS + kt * 8 + t4];
                a[mf][0] = fau(ap[0]);
                a[mf][1] = fau(ap[8 * SAS]);
                a[mf][2] = fau(ap[4]);
                a[mf][3] = fau(ap[8 * SAS + 4]);
            }
#pragma unroll
            for (int nf = 0; nf < NF; nf++) {
                const float* bp = &Bs[(wnBase + nf * 8 + g) * SAS + kt * 8 + t4];
                unsigned b0 = fau(bp[0]), b1 = fau(bp[4]);
#pragma unroll
                for (int mf = 0; mf < 2; mf++) mma8(c[mf][nf], a[mf], b0, b1);
            }
        }
        __syncthreads();
        if (last) break;
        k0 += 32;
    }

    // epilogue
#pragma unroll
    for (int mf = 0; mf < 2; mf++) {
#pragma unroll
        for (int nf = 0; nf < NF; nf++) {
            int row = m0 + wmBase + mf * 16 + g;
            int col = n0 + wnBase + nf * 8 + 2 * t4;
            float bv0 = 0.f, bv1 = 0.f;
            if constexpr (MODE != 0) { bv0 = bias[col]; bv1 = bias[col + 1]; }
            float2 o0 = { c[mf][nf][0] + bv0, c[mf][nf][1] + bv1 };
            float2 o1 = { c[mf][nf][2] + bv0, c[mf][nf][3] + bv1 };
            *(float2*)&C[(size_t)row * POSE + col] = o0;
            *(float2*)&C[(size_t)(row + 8) * POSE + col] = o1;
        }
    }
}

// ---------------- tensor-core conv(k=3,p=1) + bias + relu + BN ----------------
// A = padded weights [192, KPAD] (tf32-prep), B = shifted-window of input [128 l, 32 k].
// BM=64, BN=128, 8 warps (2m x 4n). SRC<0: input = xarg (conv1, out g_P1); else g_P1 -> g_P2.
template <int K3, int KPAD, int SRC>
__global__ __launch_bounds__(256) void tc_conv_kernel(
    const float* __restrict__ xarg,
    const float* __restrict__ cbias,
    const float* __restrict__ bng, const float* __restrict__ bnb,
    const float* __restrict__ bnm, const float* __restrict__ bnv)
{
    constexpr int IC_ = K3 / 3;
    constexpr int NF = 4;
    __shared__ __align__(16) float As[64 * SAS];
    __shared__ __align__(16) float Bs[128 * SAS];

    const float* xin = (SRC < 0) ? xarg : g_P1;
    const float* Wp = (SRC < 0) ? g_Wp1 : g_Wp2;
    float* out = (SRC < 0) ? g_P1 : g_P2;

    int m0 = blockIdx.x * 64;        // oc tile
    int l0 = blockIdx.y * 128;       // l tile
    int b = blockIdx.z;
    int t = threadIdx.x;
    const float* xb = xin + (size_t)b * IC_ * POSE;

    int arow = t >> 2, akh = (t & 3) * 8;
    const float* aptr = Wp + (size_t)(m0 + arow) * KPAD + akh;

    int w = t >> 5, lane = t & 31;
    int wm = w & 1, wn = w >> 1;
    int wmBase = wm * 32, wnBase = wn * 32;
    int g = lane >> 2, t4 = lane & 3;

    float c[2][NF][4];
#pragma unroll
    for (int mf = 0; mf < 2; mf++)
#pragma unroll
        for (int nf = 0; nf < NF; nf++)
#pragma unroll
            for (int i = 0; i < 4; i++) c[mf][nf][i] = 0.f;

    float4 ra[2];
    float vb[16];

    // initial loads (k0 = 0)
    ra[0] = *(const float4*)(aptr);
    ra[1] = *(const float4*)(aptr + 4);
#pragma unroll
    for (int i = 0; i < 16; i++) {
        int flat = i * 256 + t;
        int n = flat >> 5, kk = flat & 31;
        int k = kk;
        int ic = k / 3, r = k - ic * 3;
        int gl = l0 + n + r - 1;
        float val = 0.f;
        if (k < K3 && gl >= 0 && gl < POSE) val = xb[ic * POSE + gl];
        vb[i] = val;
    }

    int k0 = 0;
    while (true) {
        *(float4*)&As[arow * SAS + akh] = ra[0];
        *(float4*)&As[arow * SAS + akh + 4] = ra[1];
#pragma unroll
        for (int i = 0; i < 16; i++) {
            int flat = i * 256 + t;
            int n = flat >> 5, kk = flat & 31;
            Bs[n * SAS + kk] = tf32r(vb[i]);
        }
        __syncthreads();

        bool last = (k0 + 32 >= KPAD);
        if (!last) {
            ra[0] = *(const float4*)(aptr + k0 + 32);
            ra[1] = *(const float4*)(aptr + k0 + 36);
#pragma unroll
            for (int i = 0; i < 16; i++) {
                int flat = i * 256 + t;
                int n = flat >> 5, kk = flat & 31;
                int k = k0 + 32 + kk;
                int ic = k / 3, r = k - ic * 3;
                int gl = l0 + n + r - 1;
                float val = 0.f;
                if (k < K3 && gl >= 0 && gl < POSE) val = xb[ic * POSE + gl];
                vb[i] = val;
            }
        }

#pragma unroll
        for (int kt = 0; kt < 4; kt++) {
            unsigned a[2][4];
#pragma unroll
            for (int mf = 0; mf < 2; mf++) {
                const float* ap = &As[(wmBase + mf * 16 + g) * SAS + kt * 8 + t4];
                a[mf][0] = fau(ap[0]);
                a[mf][1] = fau(ap[8 * SAS]);
                a[mf][2] = fau(ap[4]);
                a[mf][3] = fau(ap[8 * SAS + 4]);
            }
#pragma unroll
            for (int nf = 0; nf < NF; nf++) {
                const float* bp = &Bs[(wnBase + nf * 8 + g) * SAS + kt * 8 + t4];
                unsigned b0 = fau(bp[0]), b1 = fau(bp[4]);
#pragma unroll
                for (int mf = 0; mf < 2; mf++) mma8(c[mf][nf], a[mf], b0, b1);
            }
        }
        __syncthreads();
        if (last) break;
        k0 += 32;
    }

    // epilogue: bias + relu + BN, guarded oc < 180
#pragma unroll
    for (int mf = 0; mf < 2; mf++) {
#pragma unroll
        for (int h = 0; h < 2; h++) {
            int oc = m0 + wmBase + mf * 16 + g + h * 8;
            if (oc < PRED) {
                float bi = cbias[oc];
                float scl = rsqrtf(bnv[oc] + EPSF) * bng[oc];
                float mm = bnm[oc], bt = bnb[oc];
                float* orow = out + ((size_t)b * PRED + oc) * POSE;
#pragma unroll
                for (int nf = 0; nf < NF; nf++) {
                    int col = l0 + wnBase + nf * 8 + 2 * t4;
                    float v0 = fmaxf(c[mf][nf][2 * h + 0] + bi, 0.f);
                    float v1 = fmaxf(c[mf][nf][2 * h + 1] + bi, 0.f);
                    float2 o = { (v0 - mm) * scl + bt, (v1 - mm) * scl + bt };
                    *(float2*)&orow[col] = o;
                }
            }
        }
    }
}

// ---------------- conv weight prep: pad to [192, KPAD], tf32-round ----------------
template <int K3, int KPAD, int WHICH>
__global__ void wprep_kernel(const float* __restrict__ w)
{
    float* Wp = (WHICH == 1) ? g_Wp1 : g_Wp2;
    int i = blockIdx.x * 256 + threadIdx.x;
    if (i >= 192 * KPAD) return;
    int oc = i / KPAD, k = i - oc * KPAD;
    Wp[i] = (oc < PRED && k < K3) ? tf32r(w[oc * K3 + k]) : 0.f;
}

// ---------------- small exact fp32 kernels ----------------
__device__ __forceinline__ float blockReduceSum(float v) {
    __shared__ float red[32];
    int lane = threadIdx.x & 31, wid = threadIdx.x >> 5;
#pragma unroll
    for (int o = 16; o > 0; o >>= 1) v += __shfl_down_sync(0xffffffffu, v, o);
    if (lane == 0) red[wid] = v;
    __syncthreads();
    int nw = (blockDim.x + 31) >> 5;
    v = (threadIdx.x < nw) ? red[threadIdx.x] : 0.f;
    if (wid == 0) {
#pragma unroll
        for (int o = 16; o > 0; o >>= 1) v += __shfl_down_sync(0xffffffffu, v, o);
        if (lane == 0) red[0] = v;
    }
    __syncthreads();
    return red[0];
}

__global__ __launch_bounds__(256) void sp_blend_kernel()
{
    int c = blockIdx.x, b = blockIdx.y;
    float* pc = g_P2 + ((size_t)b * PRED + c) * POSE;
    const float* mb = g_mem + (size_t)b * POSE;
    float s = 0.f;
    for (int d = threadIdx.x; d < POSE; d += 256) s += mb[d] * pc[d];
    float total = blockReduceSum(s);
    float sg = 1.f / (1.f + expf(-total));
    for (int d = threadIdx.x; d < POSE; d += 256)
        pc[d] = sg * pc[d] + (1.f - sg) * mb[d];
}

__global__ __launch_bounds__(256) void penc1_kernel(const float* __restrict__ w,
                                                    const float* __restrict__ bias)
{
    int n = blockIdx.x, b = blockIdx.y;
    const float* a = g_P2 + (size_t)b * PRED * POSE;
    const float* wr = w + (size_t)n * (CHUNK * POSE);
    float s = 0.f;
    for (int k = threadIdx.x; k < CHUNK * POSE; k += 256) s += a[k] * wr[k];
    float total = blockReduceSum(s);
    if (threadIdx.x == 0) g_penc1[b * CHUNK + n] = total + bias[n];
}

__global__ void penc2_kernel(const float* __restrict__ w, const float* __restrict__ bias)
{
    int b = threadIdx.x;
    float in[CHUNK];
#pragma unroll
    for (int j = 0; j < CHUNK; j++) in[j] = g_penc1[b * CHUNK + j];
#pragma unroll
    for (int n = 0; n < CHUNK; n++) {
        float s = bias[n];
#pragma unroll
        for (int j = 0; j < CHUNK; j++) s = fmaf(in[j], w[n * CHUNK + j], s);
        g_penc2[b * CHUNK + n] = s;
    }
}

__global__ __launch_bounds__(256) void gmat_kernel()
{
    int t = blockIdx.x * 256 + threadIdx.x;
    int c = t / POSE, h = t - c * POSE;
    float s = 0.f;
    for (int b = 0; b < BATCH; b++)
        s = fmaf(g_mem2[(size_t)b * POSE + h], g_penc2[b * CHUNK + c], s);
    g_G[h * CHUNK + c] = s;
}

__global__ __launch_bounds__(320) void tm_scale_kernel()
{
    __shared__ float Gs[POSE * CHUNK];
    __shared__ float sc[CHUNK];
    __shared__ float soft[CHUNK];
    int b = blockIdx.x;
    for (int i = threadIdx.x; i < POSE * CHUNK; i += 320) Gs[i] = g_G[i];
    __syncthreads();
    int wid = threadIdx.x >> 5, lane = threadIdx.x & 31;
    float s = 0.f;
    const float* mb = g_mem2 + (size_t)b * POSE;
    for (int h = lane; h < POSE; h += 32) s = fmaf(mb[h], Gs[h * CHUNK + wid], s);
#pragma unroll
    for (int o = 16; o > 0; o >>= 1) s += __shfl_down_sync(0xffffffffu, s, o);
    if (lane == 0) sc[wid] = s;
    __syncthreads();
    if (threadIdx.x == 0) {
        float mx = -1e30f;
#pragma unroll
        for (int c = 0; c < CHUNK; c++) mx = fmaxf(mx, sc[c]);
        float ssum = 0.f;
#pragma unroll
        for (int c = 0; c < CHUNK; c++) { float e = expf(sc[c] - mx); soft[c] = e; ssum += e; }
        float inv = 1.f / ssum;
#pragma unroll
        for (int c = 0; c < CHUNK; c++) soft[c] *= inv;
    }
    __syncthreads();
    float* pb = g_P2 + (size_t)b * PRED * POSE;
    for (int i = threadIdx.x; i < CHUNK * POSE; i += 320) {
        int c = i / POSE;
        pb[i] *= (1.f + soft[c]);
    }
}

__global__ void transpose_kernel(const float* __restrict__ in)
{
    __shared__ float tile[32][33];
    int x0 = blockIdx.x * 32, y0 = blockIdx.y * 32;
    for (int dy = threadIdx.y; dy < 32; dy += 8)
        tile[dy][threadIdx.x] = in[(size_t)(y0 + dy) * POSE + x0 + threadIdx.x];
    __syncthreads();
    for (int dy = threadIdx.y; dy < 32; dy += 8)
        g_W1T[(size_t)(x0 + dy) * POSE + y0 + threadIdx.x] = tile[threadIdx.x][dy];
}

__global__ void bc_kernel(const float* __restrict__ W2, const float* __restrict__ b1,
                          const float* __restrict__ b2)
{
    int d = blockIdx.x * 256 + threadIdx.x;
    if (d >= POSE) return;
    float s = 0.f;
    for (int j = 0; j < POSE; j++) s = fmaf(W2[(size_t)d * POSE + j], b1[j], s);
    g_bc[d] = s + b2[d];
}

// ---------------- launch ----------------
extern "C" void kernel_launch(void* const* d_in, const int* in_sizes, int n_in,
                              void* d_out, int out_size)
{
    const float* x       = (const float*)d_in[0];
    const float* conv1_w = (const float*)d_in[1];
    const float* conv1_b = (const float*)d_in[2];
    const float* bn1_g   = (const float*)d_in[3];
    const float* bn1_b   = (const float*)d_in[4];
    const float* bn1_m   = (const float*)d_in[5];
    const float* bn1_v   = (const float*)d_in[6];
    const float* conv2_w = (const float*)d_in[7];
    const float* conv2_b = (const float*)d_in[8];
    const float* bn2_g   = (const float*)d_in[9];
    const float* bn2_b   = (const float*)d_in[10];
    const float* bn2_m   = (const float*)d_in[11];
    const float* bn2_v   = (const float*)d_in[12];
    const float* sp_w1   = (const float*)d_in[13];
    const float* sp_b1   = (const float*)d_in[14];
    const float* sp_w2   = (const float*)d_in[15];
    const float* sp_b2   = (const float*)d_in[16];
    const float* tmc_w1  = (const float*)d_in[17];
    const float* tmc_b1  = (const float*)d_in[18];
    const float* tmc_w2  = (const float*)d_in[19];
    const float* tmc_b2  = (const float*)d_in[20];
    const float* tmm_w1  = (const float*)d_in[21];
    const float* tmm_b1  = (const float*)d_in[22];
    const float* tmm_w2  = (const float*)d_in[23];
    const float* tmm_b2  = (const float*)d_in[24];
    const float* post_w1 = (const float*)d_in[25];
    const float* post_b1 = (const float*)d_in[26];
    const float* post_w2 = (const float*)d_in[27];
    const float* post_b2 = (const float*)d_in[28];
    float* out = (float*)d_out;

    // weight prep (tf32, padded)
    wprep_kernel<180, 192, 1><<<(192 * 192 + 255) / 256, 256>>>(conv1_w);
    wprep_kernel<540, 544, 2><<<(192 * 544 + 255) / 256, 256>>>(conv2_w);

    // collapsed post_header: g_W1T = post_w1^T; g_WcT = post_w2 @ post_w1; g_bc
    transpose_kernel<<<dim3(24, 24), dim3(32, 8)>>>(post_w1);
    tc_lin_kernel<128, 0><<<dim3(6, 6), 256>>>(post_w2, nullptr, nullptr,
                                               nullptr, nullptr, nullptr);
    bc_kernel<<<3, 256>>>(post_w2, post_b1, post_b2);

    // tail linears (sp & tmc merged per launch)
    tc_lin_kernel<64, 2><<<dim3(12, 4), 256>>>(x + 50 * POSE, sp_w1, tmc_w1,
                                               sp_b1, tmc_b1, nullptr);
    tc_lin_kernel<64, 3><<<dim3(12, 4), 256>>>(nullptr, sp_w2, tmc_w2,
                                               sp_b2, tmc_b2, nullptr);

    // pred_conv
    tc_conv_kernel<180, 192, -1><<<dim3(3, 6, BATCH), 256>>>(
        x, conv1_b, bn1_g, bn1_b, bn1_m, bn1_v);
    tc_conv_kernel<540, 544, 1><<<dim3(3, 6, BATCH), 256>>>(
        nullptr, conv2_b, bn2_g, bn2_b, bn2_m, bn2_v);

    // SP memory net (in place on g_P2 chunk)
    sp_blend_kernel<<<dim3(CHUNK, BATCH), 256>>>();

    // TM memory net
    penc1_kernel<<<dim3(CHUNK, BATCH), 256>>>(tmm_w1, tmm_b1);
    penc2_kernel<<<1, BATCH>>>(tmm_w2, tmm_b2);
    gmat_kernel<<<(POSE * CHUNK) / 256, 256>>>();
    tm_scale_kernel<<<BATCH, 320>>>();

    // final: [61440, 768] @ Wc^T + bc -> out
    tc_lin_kernel<128, 1><<<dim3(6, 480), 256>>>(x, nullptr, nullptr,
                                                 nullptr, nullptr, out);
}